// round 5
// baseline (speedup 1.0000x reference)
#include <cuda_runtime.h>
#include <cuda_fp16.h>
#include <math.h>
#include <stdint.h>

// ---------------- problem constants ----------------
#define B_ 512
#define D_ 512
#define C_ 100000

#define S_F    30.0f
#define COSM_F 0.8775825618903728f
#define SINM_F 0.479425538604203f
#define TH_F  (-0.8775825618903728f)
#define MM_F   0.2397127693021015f

// ---------------- device scratch ----------------
__device__ __half g_Xh[B_ * D_];
__device__ int g_label[B_];

// ---------------- helpers ----------------
__device__ __forceinline__ uint32_t smem_u32(const void* p) {
    uint32_t a;
    asm("{ .reg .u64 t; cvta.to.shared.u64 t, %1; cvt.u32.u64 %0, t; }" : "=r"(a) : "l"(p));
    return a;
}

#define CP16(sm, gp) \
    asm volatile("cp.async.cg.shared.global [%0], [%1], 16;" \
                 :: "r"(sm), "l"(gp) : "memory")

#define LDSM4(r, addr) \
    asm volatile("ldmatrix.sync.aligned.m8n8.x4.shared.b16 {%0,%1,%2,%3}, [%4];" \
                 : "=r"((r)[0]), "=r"((r)[1]), "=r"((r)[2]), "=r"((r)[3]) : "r"(addr))

#define MMA(acc, a, b) \
    asm volatile("mma.sync.aligned.m16n8k16.row.col.f32.f16.f16.f32 " \
                 "{%0,%1,%2,%3},{%4,%5,%6,%7},{%8,%9},{%0,%1,%2,%3};" \
                 : "+f"((acc)[0]), "+f"((acc)[1]), "+f"((acc)[2]), "+f"((acc)[3]) \
                 : "r"((a)[0]), "r"((a)[1]), "r"((a)[2]), "r"((a)[3]), \
                   "r"((b)[0]), "r"((b)[1]))

__device__ __forceinline__ uint32_t h2u(__half2 h) {
    return *reinterpret_cast<uint32_t*>(&h);
}

__device__ __forceinline__ float arcf(float c, bool isl) {
    c = fminf(1.0f, fmaxf(-1.0f, c));
    float s2 = fminf(1.0f, fmaxf(1e-9f, 1.0f - c * c));
    float sn;
    asm("sqrt.approx.f32 %0, %1;" : "=f"(sn) : "f"(s2));
    float phi = c * COSM_F - sn * SINM_F;
    phi = (c > TH_F) ? phi : (c - MM_F);
    return (isl ? phi : c) * S_F;
}

// ---------------- label decode (int64 or int32 layout) ----------------
__global__ void decode_labels_kernel(const int* __restrict__ raw) {
    __shared__ int any_odd_nonzero;
    int t = threadIdx.x;  // 512
    if (t == 0) any_odd_nonzero = 0;
    __syncthreads();
    int w = raw[t];
    if ((t & 1) && (w != 0)) any_odd_nonzero = 1;
    __syncthreads();
    g_label[t] = any_odd_nonzero ? raw[t] : raw[2 * t];
}

// ---------------- X: normalize + fp16 convert ----------------
__global__ void xprep_kernel(const float* __restrict__ X) {
    int row = blockIdx.x;
    int t = threadIdx.x;  // 128
    const float4* xf = reinterpret_cast<const float4*>(X + (size_t)row * D_);
    float4 v = xf[t];
    float s = v.x * v.x + v.y * v.y + v.z * v.z + v.w * v.w;
#pragma unroll
    for (int o = 16; o > 0; o >>= 1) s += __shfl_xor_sync(0xffffffffu, s, o);
    __shared__ float ws[4];
    if ((t & 31) == 0) ws[t >> 5] = s;
    __syncthreads();
    float tot = ws[0] + ws[1] + ws[2] + ws[3];
    float inv = 1.0f / fmaxf(sqrtf(tot), 1e-12f);
    __half2 h0 = __floats2half2_rn(v.x * inv, v.y * inv);
    __half2 h1 = __floats2half2_rn(v.z * inv, v.w * inv);
    __half2* dst = reinterpret_cast<__half2*>(g_Xh + (size_t)row * D_ + t * 4);
    dst[0] = h0;
    dst[1] = h1;
}

// ---------------- fused GEMM + W-convert + ArcFace ----------------
// CTA 128x128, BK=64, 3-stage: A fp16 via cp.async, B fp32 LDG -> cvt -> STS fp16.
#define A_OFF 0
#define B_OFF 16384
#define STAGE_SZ 32768
#define NSTAGE 3
#define SMEM_TOTAL (NSTAGE * STAGE_SZ)   // 98304

__global__ __launch_bounds__(256, 2)
void arcface_fused_kernel(const float* __restrict__ W, float* __restrict__ out) {
    extern __shared__ char Smem[];
    __shared__ int slab[128];
    __shared__ float invs[128];
    const uint32_t sb = smem_u32(Smem);
    const int tid = threadIdx.x;
    const int lane = tid & 31;
    const int wid = tid >> 5;
    const int m0 = blockIdx.x * 128;   // x fastest: 4 m-tiles share W n-tile in L2
    const int n0 = blockIdx.y * 128;
    const int mW = (wid >> 2) * 64;    // warp tile 64x32
    const int nW = (wid & 3) * 32;

    if (tid < 128) slab[tid] = g_label[m0 + tid];

    float acc[4][4][4];
#pragma unroll
    for (int i = 0; i < 4; i++)
#pragma unroll
        for (int j = 0; j < 4; j++)
#pragma unroll
            for (int q = 0; q < 4; q++) acc[i][j][q] = 0.0f;

    // producer indices (per 16B fp16 chunk / per 8-float fp32 chunk)
    // idx = tid + 256*j -> row r = idx>>3 (0..127), chunk c = idx&7
    float4 br[4][2];          // B staging: 4 rows x 8 floats
    float ssq[4] = {0.f, 0.f, 0.f, 0.f};

    // ldmatrix lane-address components
    const int arow = mW + (lane & 7) + ((lane >> 3) & 1) * 8;   // + 16*i
    const int acol = ((lane >> 4) & 1) * 16;
    const int brow = nW + ((lane >> 4) & 1) * 8 + (lane & 7);   // + 16*jp
    const int bcol = ((lane >> 3) & 1) * 16;
    const int sx   = (lane & 7) * 16;

    auto ldgB = [&](int kc) {
#pragma unroll
        for (int j = 0; j < 4; j++) {
            int idx = tid + 256 * j;
            int r = idx >> 3, c = idx & 7;
            int n = n0 + r;
            if (n < C_) {
                const float4* p = reinterpret_cast<const float4*>(
                    W + (size_t)n * D_ + kc * 64 + c * 8);
                br[j][0] = p[0];
                br[j][1] = p[1];
            } else {
                br[j][0] = make_float4(0.f, 0.f, 0.f, 0.f);
                br[j][1] = br[j][0];
            }
        }
    };

    auto stsB = [&](int st) {
        char* base = Smem + st * STAGE_SZ + B_OFF;
#pragma unroll
        for (int j = 0; j < 4; j++) {
            int idx = tid + 256 * j;
            int r = idx >> 3, c = idx & 7;
            float4 f0 = br[j][0], f1 = br[j][1];
            ssq[j] += f0.x * f0.x + f0.y * f0.y + f0.z * f0.z + f0.w * f0.w
                    + f1.x * f1.x + f1.y * f1.y + f1.z * f1.z + f1.w * f1.w;
            uint4 hv;
            hv.x = h2u(__floats2half2_rn(f0.x, f0.y));
            hv.y = h2u(__floats2half2_rn(f0.z, f0.w));
            hv.z = h2u(__floats2half2_rn(f1.x, f1.y));
            hv.w = h2u(__floats2half2_rn(f1.z, f1.w));
            uint32_t doff = (uint32_t)(r * 128 + ((c * 16) ^ ((r & 7) * 16)));
            *reinterpret_cast<uint4*>(base + doff) = hv;
        }
    };

    auto cpA = [&](int kc, int st) {
        uint32_t base = sb + st * STAGE_SZ + A_OFF;
#pragma unroll
        for (int j = 0; j < 4; j++) {
            int idx = tid + 256 * j;
            int r = idx >> 3, c = idx & 7;
            uint32_t doff = (uint32_t)(r * 128 + ((c * 16) ^ ((r & 7) * 16)));
            size_t abyt = (size_t)(m0 + r) * (D_ * 2) + kc * 128 + c * 16;
            CP16(base + doff, (const char*)g_Xh + abyt);
        }
    };

    auto compute_stage = [&](int st) {
        const uint32_t Ab = sb + st * STAGE_SZ + A_OFF;
        const uint32_t Bb = sb + st * STAGE_SZ + B_OFF;
#pragma unroll
        for (int g = 0; g < 4; g++) {
            uint32_t bh[4][2];
#pragma unroll
            for (int jp = 0; jp < 2; jp++) {
                uint32_t boff = (uint32_t)((brow + 16 * jp) * 128 + ((g * 32 + bcol) ^ sx));
                uint32_t t4[4];
                LDSM4(t4, Bb + boff);
                bh[2 * jp][0] = t4[0]; bh[2 * jp][1] = t4[1];
                bh[2 * jp + 1][0] = t4[2]; bh[2 * jp + 1][1] = t4[3];
            }
#pragma unroll
            for (int i = 0; i < 4; i++) {
                uint32_t a4[4];
                uint32_t aoff = (uint32_t)((arow + 16 * i) * 128 + ((g * 32 + acol) ^ sx));
                LDSM4(a4, Ab + aoff);
#pragma unroll
                for (int j = 0; j < 4; j++) MMA(acc[i][j], a4, bh[j]);
            }
        }
    };

    // ---- prologue: fill stages 0..2 ----
    ldgB(0);
    cpA(0, 0);
    asm volatile("cp.async.commit_group;" ::: "memory");
    cpA(1, 1);
    asm volatile("cp.async.commit_group;" ::: "memory");
    cpA(2, 2);
    asm volatile("cp.async.commit_group;" ::: "memory");
    stsB(0);
    ldgB(1); stsB(1);
    ldgB(2); stsB(2);
    asm volatile("cp.async.wait_group 2;" ::: "memory");
    __syncthreads();

    // ---- main loop ----
    for (int kc = 0; kc < 8; kc++) {
        if (kc + 3 < 8) ldgB(kc + 3);
        compute_stage(kc % 3);
        __syncthreads();
        if (kc + 3 < 8) {
            stsB(kc % 3);
            cpA(kc + 3, kc % 3);
        }
        asm volatile("cp.async.commit_group;" ::: "memory");
        asm volatile("cp.async.wait_group 2;" ::: "memory");
        __syncthreads();
    }

    // ---- W row inverse norms ----
#pragma unroll
    for (int j = 0; j < 4; j++) {
        float s = ssq[j];
        s += __shfl_xor_sync(0xffffffffu, s, 1);
        s += __shfl_xor_sync(0xffffffffu, s, 2);
        s += __shfl_xor_sync(0xffffffffu, s, 4);
        if ((tid & 7) == 0) invs[(tid + 256 * j) >> 3] = 1.0f / fmaxf(sqrtf(s), 1e-12f);
    }
    __syncthreads();

    // ---- epilogue: ArcFace + direct stores ----
#pragma unroll
    for (int i = 0; i < 4; i++) {
        int lm = mW + i * 16 + (lane >> 2);
        int gm = m0 + lm;
        int lab0 = slab[lm];
        int lab1 = slab[lm + 8];
#pragma unroll
        for (int j = 0; j < 4; j++) {
            int colL = nW + j * 8 + (lane & 3) * 2;
            int col = n0 + colL;
            if (col < C_) {   // C_ even -> pair stays in-bounds together
                float i0 = invs[colL], i1 = invs[colL + 1];
                float2 v0, v1;
                v0.x = arcf(acc[i][j][0] * i0, col == lab0);
                v0.y = arcf(acc[i][j][1] * i1, col + 1 == lab0);
                v1.x = arcf(acc[i][j][2] * i0, col == lab1);
                v1.y = arcf(acc[i][j][3] * i1, col + 1 == lab1);
                *reinterpret_cast<float2*>(out + (size_t)gm * C_ + col) = v0;
                *reinterpret_cast<float2*>(out + (size_t)(gm + 8) * C_ + col) = v1;
            }
        }
    }
}

// ---------------- launch ----------------
extern "C" void kernel_launch(void* const* d_in, const int* in_sizes, int n_in,
                              void* d_out, int out_size) {
    const float* X = nullptr;
    const float* W = nullptr;
    const void*  L = nullptr;

    for (int i = 0; i < n_in; i++) {
        int s = in_sizes[i];
        if (s == B_ * D_)      X = (const float*)d_in[i];
        else if (s == C_ * D_) W = (const float*)d_in[i];
        else if (s == B_)      L = d_in[i];
    }
    if (!X) X = (const float*)d_in[0];
    if (!L) L = d_in[1];
    if (!W) W = (const float*)d_in[2];

    float* out = (float*)d_out;

    decode_labels_kernel<<<1, 512>>>((const int*)L);
    xprep_kernel<<<B_, 128>>>(X);

    cudaFuncSetAttribute(arcface_fused_kernel,
                         cudaFuncAttributeMaxDynamicSharedMemorySize, SMEM_TOTAL);
    dim3 grid(4, (C_ + 127) / 128);   // x = m-tile (fast) for W L2 reuse
    arcface_fused_kernel<<<grid, 256, SMEM_TOTAL>>>(W, out);
    (void)out_size;
}

// round 6
// speedup vs baseline: 1.2160x; 1.2160x over previous
#include <cuda_runtime.h>
#include <cuda_fp16.h>
#include <math.h>
#include <stdint.h>

// ---------------- problem constants ----------------
#define B_ 512
#define D_ 512
#define C_ 100000

#define S_F    30.0f
#define COSM_F 0.8775825618903728f
#define SINM_F 0.479425538604203f
#define TH_F  (-0.8775825618903728f)
#define MM_F   0.2397127693021015f

// ---------------- device scratch ----------------
__device__ __half g_Xh[B_ * D_];
__device__ __half g_Wh[(size_t)C_ * D_];
__device__ int g_label[B_];

// ---------------- helpers ----------------
__device__ __forceinline__ uint32_t smem_u32(const void* p) {
    uint32_t a;
    asm("{ .reg .u64 t; cvta.to.shared.u64 t, %1; cvt.u32.u64 %0, t; }" : "=r"(a) : "l"(p));
    return a;
}

#define CP16(sm, gp, sz) \
    asm volatile("cp.async.cg.shared.global [%0], [%1], 16, %2;" \
                 :: "r"(sm), "l"(gp), "r"(sz) : "memory")

#define LDSM4(r, addr) \
    asm volatile("ldmatrix.sync.aligned.m8n8.x4.shared.b16 {%0,%1,%2,%3}, [%4];" \
                 : "=r"((r)[0]), "=r"((r)[1]), "=r"((r)[2]), "=r"((r)[3]) : "r"(addr))

#define MMA(acc, a, b) \
    asm volatile("mma.sync.aligned.m16n8k16.row.col.f32.f16.f16.f32 " \
                 "{%0,%1,%2,%3},{%4,%5,%6,%7},{%8,%9},{%0,%1,%2,%3};" \
                 : "+f"((acc)[0]), "+f"((acc)[1]), "+f"((acc)[2]), "+f"((acc)[3]) \
                 : "r"((a)[0]), "r"((a)[1]), "r"((a)[2]), "r"((a)[3]), \
                   "r"((b)[0]), "r"((b)[1]))

__device__ __forceinline__ uint32_t h2u(__half2 h) {
    return *reinterpret_cast<uint32_t*>(&h);
}

__device__ __forceinline__ float arcf(float c, bool isl) {
    c = fminf(1.0f, fmaxf(-1.0f, c));
    float s2 = fminf(1.0f, fmaxf(1e-9f, 1.0f - c * c));
    float sn;
    asm("sqrt.approx.f32 %0, %1;" : "=f"(sn) : "f"(s2));
    float phi = c * COSM_F - sn * SINM_F;
    phi = (c > TH_F) ? phi : (c - MM_F);
    return (isl ? phi : c) * S_F;
}

// ---------------- X: normalize + fp16 convert + label decode ----------------
// One block per row (512 blocks, 128 threads). Thread 0 also decodes this
// row's label: reads 8 odd int32 words of the label buffer; all-zero =>
// int64 layout (p(false positive for random labels) ~ 1e-40).
__global__ void xprep_kernel(const float* __restrict__ X, const int* __restrict__ raw) {
    int row = blockIdx.x;
    int t = threadIdx.x;  // 128
    const float4* xf = reinterpret_cast<const float4*>(X + (size_t)row * D_);
    float4 v = xf[t];
    float s = v.x * v.x + v.y * v.y + v.z * v.z + v.w * v.w;
#pragma unroll
    for (int o = 16; o > 0; o >>= 1) s += __shfl_xor_sync(0xffffffffu, s, o);
    __shared__ float ws[4];
    if ((t & 31) == 0) ws[t >> 5] = s;
    __syncthreads();
    float tot = ws[0] + ws[1] + ws[2] + ws[3];
    float inv = 1.0f / fmaxf(sqrtf(tot), 1e-12f);
    __half2 h0 = __floats2half2_rn(v.x * inv, v.y * inv);
    __half2 h1 = __floats2half2_rn(v.z * inv, v.w * inv);
    uint2 hv;
    hv.x = h2u(h0);
    hv.y = h2u(h1);
    *reinterpret_cast<uint2*>(g_Xh + (size_t)row * D_ + t * 4) = hv;

    if (t == 0) {
        int odd = raw[1] | raw[3] | raw[5] | raw[7] | raw[9] | raw[11] | raw[13] | raw[15];
        g_label[row] = (odd == 0) ? raw[2 * row] : raw[row];
    }
}

// ---------------- W: normalize + fp16 convert (2 rows per block) ----------
__global__ __launch_bounds__(256)
void wprep_kernel(const float* __restrict__ W) {
    int h = threadIdx.x >> 7;          // 0/1: which row
    int t = threadIdx.x & 127;         // 128 threads per row
    int row = blockIdx.x * 2 + h;      // C_ even -> always valid
    const float4* wf = reinterpret_cast<const float4*>(W + (size_t)row * D_);
    float4 v = wf[t];
    float s = v.x * v.x + v.y * v.y + v.z * v.z + v.w * v.w;
#pragma unroll
    for (int o = 16; o > 0; o >>= 1) s += __shfl_xor_sync(0xffffffffu, s, o);
    __shared__ float ws[8];
    if ((t & 31) == 0) ws[h * 4 + (t >> 5)] = s;
    __syncthreads();
    float tot = ws[h * 4 + 0] + ws[h * 4 + 1] + ws[h * 4 + 2] + ws[h * 4 + 3];
    float inv = 1.0f / fmaxf(sqrtf(tot), 1e-12f);
    uint2 hv;
    hv.x = h2u(__floats2half2_rn(v.x * inv, v.y * inv));
    hv.y = h2u(__floats2half2_rn(v.z * inv, v.w * inv));
    *reinterpret_cast<uint2*>(g_Wh + (size_t)row * D_ + t * 4) = hv;
}

// ---------------- GEMM + ArcFace (single-product fp16 mma.sync) -----------
// CTA 128x128, BK=64 fp16 (128B rows, SW128 swizzle), 3-stage cp.async,
// single __syncthreads per k-chunk, 2 CTAs/SM.
#define A_OFF 0
#define B_OFF 16384
#define STAGE_SZ 32768
#define NSTAGE 3
#define SMEM_TOTAL (NSTAGE * STAGE_SZ)   // 98304

__global__ __launch_bounds__(256, 2)
void arcface_mma_kernel(float* __restrict__ out) {
    extern __shared__ char Smem[];
    __shared__ int slab[128];
    const uint32_t sb = smem_u32(Smem);
    const int tid = threadIdx.x;
    const int lane = tid & 31;
    const int wid = tid >> 5;
    const int m0 = blockIdx.x * 128;   // x fastest -> 4 m-tiles share W n-tile in L2
    const int n0 = blockIdx.y * 128;
    const int mW = (wid >> 2) * 64;    // warp tile 64x32
    const int nW = (wid & 3) * 32;

    if (tid < 128) slab[tid] = g_label[m0 + tid];

    float acc[4][4][4];
#pragma unroll
    for (int i = 0; i < 4; i++)
#pragma unroll
        for (int j = 0; j < 4; j++)
#pragma unroll
            for (int q = 0; q < 4; q++) acc[i][j][q] = 0.0f;

    // ldmatrix lane-address components
    const int arow = mW + (lane & 7) + ((lane >> 3) & 1) * 8;   // + 16*i
    const int acol = ((lane >> 4) & 1) * 16;                    // + 32*g
    const int brow = nW + ((lane >> 4) & 1) * 8 + (lane & 7);   // + 16*jp
    const int bcol = ((lane >> 3) & 1) * 16;
    const int sx   = (lane & 7) * 16;                           // swizzle xor

    auto load_stage = [&](int kc, int st) {
        uint32_t base = sb + st * STAGE_SZ;
#pragma unroll
        for (int j = 0; j < 4; j++) {
            int idx = tid + 256 * j;
            int r = idx >> 3, c = idx & 7;
            uint32_t doff = (uint32_t)(r * 128 + ((c * 16) ^ ((r & 7) * 16)));
            size_t abyt = (size_t)(m0 + r) * (D_ * 2) + kc * 128 + c * 16;
            CP16(base + A_OFF + doff, (const char*)g_Xh + abyt, 16);
            int n = n0 + r;
            int ok = (n < C_) ? 16 : 0;
            int nn = (n < C_) ? n : 0;
            size_t bbyt = (size_t)nn * (D_ * 2) + kc * 128 + c * 16;
            CP16(base + B_OFF + doff, (const char*)g_Wh + bbyt, ok);
        }
    };

    auto compute_stage = [&](int st) {
        const uint32_t Ab = sb + st * STAGE_SZ + A_OFF;
        const uint32_t Bb = sb + st * STAGE_SZ + B_OFF;
#pragma unroll
        for (int g = 0; g < 4; g++) {
            uint32_t bh[4][2];
#pragma unroll
            for (int jp = 0; jp < 2; jp++) {
                uint32_t boff = (uint32_t)((brow + 16 * jp) * 128 + ((g * 32 + bcol) ^ sx));
                uint32_t t4[4];
                LDSM4(t4, Bb + boff);
                bh[2 * jp][0] = t4[0]; bh[2 * jp][1] = t4[1];
                bh[2 * jp + 1][0] = t4[2]; bh[2 * jp + 1][1] = t4[3];
            }
#pragma unroll
            for (int i = 0; i < 4; i++) {
                uint32_t a4[4];
                uint32_t aoff = (uint32_t)((arow + 16 * i) * 128 + ((g * 32 + acol) ^ sx));
                LDSM4(a4, Ab + aoff);
#pragma unroll
                for (int j = 0; j < 4; j++) MMA(acc[i][j], a4, bh[j]);
            }
        }
    };

    // ---- prologue: stages 0,1 in flight ----
    load_stage(0, 0);
    asm volatile("cp.async.commit_group;" ::: "memory");
    load_stage(1, 1);
    asm volatile("cp.async.commit_group;" ::: "memory");

    // ---- main loop: single barrier per iteration ----
    // At iter kc: wait for chunk kc's loads; barrier (also protects stage
    // (kc-1)%3, computed last iter, now the target of chunk kc+2's loads);
    // issue loads kc+2 -> stage (kc+2)%3; compute stage kc%3.
    for (int kc = 0; kc < 8; kc++) {
        asm volatile("cp.async.wait_group 1;" ::: "memory");
        __syncthreads();
        if (kc + 2 < 8) load_stage(kc + 2, (kc + 2) % 3);
        asm volatile("cp.async.commit_group;" ::: "memory");
        compute_stage(kc % 3);
    }

    // ---- epilogue: ArcFace + direct stores ----
#pragma unroll
    for (int i = 0; i < 4; i++) {
        int lm = mW + i * 16 + (lane >> 2);
        int gm = m0 + lm;
        int lab0 = slab[lm];
        int lab1 = slab[lm + 8];
#pragma unroll
        for (int j = 0; j < 4; j++) {
            int col = n0 + nW + j * 8 + (lane & 3) * 2;
            if (col < C_) {   // C_ even -> pair stays in-bounds together
                float2 v0, v1;
                v0.x = arcf(acc[i][j][0], col == lab0);
                v0.y = arcf(acc[i][j][1], col + 1 == lab0);
                v1.x = arcf(acc[i][j][2], col == lab1);
                v1.y = arcf(acc[i][j][3], col + 1 == lab1);
                *reinterpret_cast<float2*>(out + (size_t)gm * C_ + col) = v0;
                *reinterpret_cast<float2*>(out + (size_t)(gm + 8) * C_ + col) = v1;
            }
        }
    }
}

// ---------------- launch ----------------
extern "C" void kernel_launch(void* const* d_in, const int* in_sizes, int n_in,
                              void* d_out, int out_size) {
    const float* X = nullptr;
    const float* W = nullptr;
    const void*  L = nullptr;

    for (int i = 0; i < n_in; i++) {
        int s = in_sizes[i];
        if (s == B_ * D_)      X = (const float*)d_in[i];
        else if (s == C_ * D_) W = (const float*)d_in[i];
        else if (s == B_)      L = d_in[i];
    }
    if (!X) X = (const float*)d_in[0];
    if (!L) L = d_in[1];
    if (!W) W = (const float*)d_in[2];

    float* out = (float*)d_out;

    xprep_kernel<<<B_, 128>>>(X, (const int*)L);
    wprep_kernel<<<C_ / 2, 256>>>(W);

    cudaFuncSetAttribute(arcface_mma_kernel,
                         cudaFuncAttributeMaxDynamicSharedMemorySize, SMEM_TOTAL);
    dim3 grid(4, (C_ + 127) / 128);   // x = m-tile (fast) for W L2 reuse
    arcface_mma_kernel<<<grid, 256, SMEM_TOTAL>>>(out);
    (void)out_size;
}